// round 16
// baseline (speedup 1.0000x reference)
#include <cuda_runtime.h>
#include <cuda_fp16.h>
#include <cstdint>

#define NN 32768
#define HH 2048
#define DD 256
#define KK 4096
#define TAU 0.1f
#define TAU2 0.045f

typedef unsigned long long u64;

// ------------------------------------------------------------------ scratch
__device__ float g_z[(size_t)NN * DD];
__device__ int   g_idx[NN];
__device__ float g_gap[NN];
__device__ float g_gap2[NN];
__device__ float g_cnorm[KK];
__device__ float g_partial[256];

__device__ __align__(16) __half g_embS[2][(size_t)NN * HH];
__device__ __align__(16) __half g_zS[2][(size_t)NN * DD];
__device__ __align__(16) __half g_cbS[2][(size_t)KK * DD];
__device__ __align__(16) __half g_pwS[2][(size_t)DD * HH];
__device__ __align__(16) __half g_qwS[2][(size_t)HH * DD];

// ------------------------------------------------------------------ helpers
__device__ __forceinline__ void ldm_x4(uint32_t (&r)[4], uint32_t addr) {
    asm volatile("ldmatrix.sync.aligned.m8n8.x4.shared.b16 {%0,%1,%2,%3}, [%4];"
                 : "=r"(r[0]), "=r"(r[1]), "=r"(r[2]), "=r"(r[3]) : "r"(addr));
}

__device__ __forceinline__ void mma16816(float (&d)[4], const uint32_t (&a)[4],
                                         uint32_t b0, uint32_t b1) {
    asm volatile(
        "mma.sync.aligned.m16n8k16.row.col.f32.f16.f16.f32 "
        "{%0,%1,%2,%3}, {%4,%5,%6,%7}, {%8,%9}, {%0,%1,%2,%3};"
        : "+f"(d[0]), "+f"(d[1]), "+f"(d[2]), "+f"(d[3])
        : "r"(a[0]), "r"(a[1]), "r"(a[2]), "r"(a[3]), "r"(b0), "r"(b1));
}

__device__ __forceinline__ void cp16(uint32_t saddr, const void* g) {
    asm volatile("cp.async.cg.shared.global [%0], [%1], 16;" :: "r"(saddr), "l"(g));
}

__device__ __forceinline__ u64 pack_key(float sc, int col) {
    unsigned u = __float_as_uint(sc);
    u = (u & 0x80000000u) ? ~u : (u | 0x80000000u);
    return ((u64)u << 32) | (unsigned)col;
}

__device__ __forceinline__ float key_score(u64 k) {
    unsigned u = (unsigned)(k >> 32);
    u = (u & 0x80000000u) ? (u & 0x7FFFFFFFu) : ~u;
    return __uint_as_float(u);
}

__device__ __forceinline__ void upd2(u64& m1, u64& m2, u64 key) {
    if (key < m1) { m2 = m1; m1 = key; }
    else if (key < m2) m2 = key;
}

__device__ __forceinline__ void merge2(u64& a1, u64& a2, u64 b1, u64 b2) {
    u64 n1, n2;
    if (a1 <= b1) { n1 = a1; n2 = (a2 < b1 ? a2 : b1); }
    else          { n1 = b1; n2 = (b2 < a1 ? b2 : a1); }
    a1 = n1; a2 = n2;
}

// ------------------------------------------------------------------ split (fp32 -> 2 fp16 planes)
template <int W>
__global__ __launch_bounds__(256) void split_kernel(const float* __restrict__ src_in, size_t n8)
{
    __half *p0, *p1;
    const float* src = src_in;
    if (W == 0)      { p0 = g_embS[0]; p1 = g_embS[1]; }
    else if (W == 1) { p0 = g_pwS[0];  p1 = g_pwS[1]; }
    else if (W == 2) { p0 = g_cbS[0];  p1 = g_cbS[1]; }
    else if (W == 3) { p0 = g_qwS[0];  p1 = g_qwS[1]; }
    else             { p0 = g_zS[0];   p1 = g_zS[1]; src = g_z; }

    for (size_t i = blockIdx.x * (size_t)blockDim.x + threadIdx.x; i < n8;
         i += (size_t)gridDim.x * blockDim.x) {
        float4 a = ((const float4*)src)[2 * i];
        float4 b = ((const float4*)src)[2 * i + 1];
        float v[8] = {a.x, a.y, a.z, a.w, b.x, b.y, b.z, b.w};
        unsigned short s0[8], s1[8];
#pragma unroll
        for (int j = 0; j < 8; j++) {
            float x = v[j];
            __half h0 = __float2half_rn(x);
            float r = x - __half2float(h0);
            __half h1 = __float2half_rn(r);
            s0[j] = __half_as_ushort(h0);
            s1[j] = __half_as_ushort(h1);
        }
        uint4 u0, u1;
        u0.x = s0[0] | ((uint32_t)s0[1] << 16); u0.y = s0[2] | ((uint32_t)s0[3] << 16);
        u0.z = s0[4] | ((uint32_t)s0[5] << 16); u0.w = s0[6] | ((uint32_t)s0[7] << 16);
        u1.x = s1[0] | ((uint32_t)s1[1] << 16); u1.y = s1[2] | ((uint32_t)s1[3] << 16);
        u1.z = s1[4] | ((uint32_t)s1[5] << 16); u1.w = s1[6] | ((uint32_t)s1[7] << 16);
        ((uint4*)p0)[i] = u0;
        ((uint4*)p1)[i] = u1;
    }
}

// ------------------------------------------------------------------ mma GEMM, 512 threads, unified 2-pass (a0+a1)*b0
// MODE 0: z = embed @ pre_w.T + pre_b   (K=2048)
// MODE 1: argmin_k ||c||^2 - 2 z.c      (K=256, 32 n-tiles) + gap
// MODE 2: out = cb[idx] @ post_w.T + b  (K=256)
#define PLANEB 16384
#define STAGEB (4 * PLANEB)   // 64 KB stride; plane slot 3 never loaded
#define DSMEM  (2 * STAGEB)   // 128 KB

template <int MODE>
__global__ __launch_bounds__(512, 1) void mm_kernel(const float* __restrict__ bias,
                                                    float* __restrict__ Cout)
{
    constexpr int Kd  = (MODE == 0) ? HH : DD;
    constexpr int KCH = Kd / 64;
    constexpr int NT  = (MODE == 1) ? (KK / 128) : 1;
    constexpr int TOT = KCH * NT;
    constexpr size_t SA = (MODE == 0) ? (size_t)NN * HH
                        : (MODE == 1) ? (size_t)NN * DD : (size_t)KK * DD;

    extern __shared__ __align__(1024) char dsm[];
    __shared__ int rmap[128];
    __shared__ u64 red1[128][4];
    __shared__ u64 red2[128][4];

    const int tid = threadIdx.x;
    const int wid = tid >> 5, lane = tid & 31;
    const int wm = wid >> 2, wn = wid & 3;        // 4x4 warp grid, 32x32 tiles
    const int m0 = blockIdx.x * 128;
    const int n0b = blockIdx.y * 128;

    const __half* Abase =
        (MODE == 0) ? g_embS[0] : (MODE == 1) ? g_zS[0] : g_cbS[0];
    const __half* Bbase =
        (MODE == 0) ? g_pwS[0] : (MODE == 1) ? g_cbS[0] : g_qwS[0];

    if (MODE == 2) {
        if (tid < 128) rmap[tid] = g_idx[m0 + tid];
        __syncthreads();
    }

    const uint32_t dsm_u = (uint32_t)__cvta_generic_to_shared(dsm);

    auto issue = [&](int s) {
        const int nt = s / KCH;
        const int k0 = (s % KCH) * 64;
        const int n0 = (MODE == 1) ? nt * 128 : n0b;
        const uint32_t st = dsm_u + (s & 1) * STAGEB;
#pragma unroll
        for (int i = 0; i < 8; i++) {
            int lin = tid + i * 512;          // 0..4095 = 4 plane slots x 128 rows x 8 ch
            int p = lin >> 10, rem = lin & 1023, row = rem >> 3, ch = rem & 7;
            if (p == 3) continue;             // only A0, A1, B0
            const __half* g;
            if (p < 2) {
                int grow = (MODE == 2) ? rmap[row] : (m0 + row);
                g = Abase + (size_t)p * SA + (size_t)grow * Kd + k0 + ch * 8;
            } else {
                g = Bbase + (size_t)(n0 + row) * Kd + k0 + ch * 8;
            }
            uint32_t sa = st + p * PLANEB + row * 128 + ((ch ^ (row & 7)) << 4);
            cp16(sa, g);
        }
        asm volatile("cp.async.commit_group;");
    };

    float acc[2][4][4];
#pragma unroll
    for (int mt = 0; mt < 2; mt++)
#pragma unroll
        for (int nf = 0; nf < 4; nf++)
#pragma unroll
            for (int q = 0; q < 4; q++) acc[mt][nf][q] = 0.f;

    u64 rm1[2][2], rm2[2][2];
    if (MODE == 1) {
#pragma unroll
        for (int mt = 0; mt < 2; mt++)
#pragma unroll
            for (int h = 0; h < 2; h++) { rm1[mt][h] = ~0ULL; rm2[mt][h] = ~0ULL; }
    }

    issue(0);
    issue(1);

    for (int s = 0; s < TOT; s++) {
        if (s == TOT - 1) asm volatile("cp.async.wait_group 0;");
        else              asm volatile("cp.async.wait_group 1;");
        __syncthreads();

        const uint32_t sbase = dsm_u + (s & 1) * STAGEB;
#pragma unroll
        for (int kk = 0; kk < 4; kk++) {
            uint32_t Af[2][2][4];
            uint32_t Bf[2][4];
#pragma unroll
            for (int p = 0; p < 2; p++)
#pragma unroll
                for (int mt = 0; mt < 2; mt++) {
                    int row = wm * 32 + mt * 16 + (lane & 15);
                    int ch = kk * 2 + (lane >> 4);
                    ldm_x4(Af[p][mt],
                           sbase + p * PLANEB + row * 128 + ((ch ^ (row & 7)) << 4));
                }
#pragma unroll
            for (int n2 = 0; n2 < 2; n2++) {
                int row = wn * 32 + n2 * 16 + (lane & 7) + ((lane >> 4) << 3);
                int ch = kk * 2 + ((lane >> 3) & 1);
                ldm_x4(Bf[n2],
                       sbase + 2 * PLANEB + row * 128 + ((ch ^ (row & 7)) << 4));
            }
            // 2 passes: a0*b0 + a1*b0
#pragma unroll
            for (int pp = 0; pp < 2; pp++)
#pragma unroll
                for (int mt = 0; mt < 2; mt++)
#pragma unroll
                    for (int nf = 0; nf < 4; nf++)
                        mma16816(acc[mt][nf], Af[pp][mt],
                                 Bf[nf >> 1][(nf & 1) * 2],
                                 Bf[nf >> 1][(nf & 1) * 2 + 1]);
        }

        if (MODE == 1 && (s % KCH) == KCH - 1) {
            const int nt = s / KCH;
#pragma unroll
            for (int nf = 0; nf < 4; nf++) {
                int col = nt * 128 + wn * 32 + nf * 8 + (lane & 3) * 2;
                float cn0 = __ldg(&g_cnorm[col]);
                float cn1 = __ldg(&g_cnorm[col + 1]);
#pragma unroll
                for (int mt = 0; mt < 2; mt++) {
                    upd2(rm1[mt][0], rm2[mt][0], pack_key(cn0 - 2.f * acc[mt][nf][0], col));
                    upd2(rm1[mt][0], rm2[mt][0], pack_key(cn1 - 2.f * acc[mt][nf][1], col + 1));
                    upd2(rm1[mt][1], rm2[mt][1], pack_key(cn0 - 2.f * acc[mt][nf][2], col));
                    upd2(rm1[mt][1], rm2[mt][1], pack_key(cn1 - 2.f * acc[mt][nf][3], col + 1));
                    acc[mt][nf][0] = 0.f; acc[mt][nf][1] = 0.f;
                    acc[mt][nf][2] = 0.f; acc[mt][nf][3] = 0.f;
                }
            }
        }

        __syncthreads();
        if (s + 2 < TOT) issue(s + 2);
    }

    if (MODE == 1) {
#pragma unroll
        for (int mt = 0; mt < 2; mt++)
#pragma unroll
            for (int h = 0; h < 2; h++) {
                u64 a1 = rm1[mt][h], a2 = rm2[mt][h];
#pragma unroll
                for (int off = 1; off <= 2; off <<= 1) {
                    u64 b1 = __shfl_xor_sync(0xFFFFFFFFu, a1, off);
                    u64 b2 = __shfl_xor_sync(0xFFFFFFFFu, a2, off);
                    merge2(a1, a2, b1, b2);
                }
                if ((lane & 3) == 0) {
                    int r = wm * 32 + mt * 16 + h * 8 + (lane >> 2);
                    red1[r][wn] = a1;
                    red2[r][wn] = a2;
                }
            }
        __syncthreads();
        if (tid < 128) {
            u64 a1 = red1[tid][0], a2 = red2[tid][0];
#pragma unroll
            for (int j = 1; j < 4; j++) merge2(a1, a2, red1[tid][j], red2[tid][j]);
            int idx = (int)(a1 & 0xFFFFFFFFu);
            g_idx[m0 + tid] = idx;
            Cout[m0 + tid] = (float)idx;
            g_gap[m0 + tid] = key_score(a2) - key_score(a1);
        }
    } else {
        float* C = (MODE == 0) ? g_z : Cout;
        const int ldC = (MODE == 0) ? DD : HH;
#pragma unroll
        for (int mt = 0; mt < 2; mt++)
#pragma unroll
            for (int nf = 0; nf < 4; nf++) {
                int col = n0b + wn * 32 + nf * 8 + (lane & 3) * 2;
                int r0 = m0 + wm * 32 + mt * 16 + (lane >> 2);
                float b0v = __ldg(&bias[col]);
                float b1v = __ldg(&bias[col + 1]);
                float2 v0 = {acc[mt][nf][0] + b0v, acc[mt][nf][1] + b1v};
                float2 v1 = {acc[mt][nf][2] + b0v, acc[mt][nf][3] + b1v};
                *(float2*)&C[(size_t)r0 * ldC + col] = v0;
                *(float2*)&C[(size_t)(r0 + 8) * ldC + col] = v1;
            }
    }
}

// ------------------------------------------------------------------ tier-1 rescue: exact fp32 from g_z
__global__ __launch_bounds__(256) void rescue32_kernel(const float* __restrict__ CB,
                                                       float* __restrict__ out_idx)
{
    const int row = blockIdx.x;
    if (g_gap[row] >= TAU) return;

    __shared__ float zrow[DD];
    __shared__ u64 w1[8], w2[8];
    const int tid = threadIdx.x, wid = tid >> 5, lane = tid & 31;

    if (tid < DD / 4)
        ((float4*)zrow)[tid] = ((const float4*)(g_z + (size_t)row * DD))[tid];
    __syncthreads();

    u64 b1 = ~0ULL, b2 = ~0ULL;
    for (int c = wid; c < KK; c += 8) {
        const float4* cp = (const float4*)(CB + (size_t)c * DD);
        float s = 0.f;
#pragma unroll
        for (int i = 0; i < 2; i++) {
            float4 cv = cp[lane + 32 * i];
            float4 zv = ((const float4*)zrow)[lane + 32 * i];
            s += cv.x * zv.x + cv.y * zv.y + cv.z * zv.z + cv.w * zv.w;
        }
#pragma unroll
        for (int o = 16; o; o >>= 1) s += __shfl_xor_sync(0xFFFFFFFFu, s, o);
        upd2(b1, b2, pack_key(__ldg(&g_cnorm[c]) - 2.f * s, c));
    }
    if (lane == 0) { w1[wid] = b1; w2[wid] = b2; }
    __syncthreads();
    if (tid == 0) {
        u64 a1 = w1[0], a2 = w2[0];
#pragma unroll
        for (int i = 1; i < 8; i++) merge2(a1, a2, w1[i], w2[i]);
        int idx = (int)(a1 & 0xFFFFFFFFu);
        g_idx[row] = idx;
        out_idx[row] = (float)idx;
        g_gap2[row] = key_score(a2) - key_score(a1);
    }
}

// ------------------------------------------------------------------ tier-2 rescue: fp64 from embed (proven)
__global__ __launch_bounds__(256) void rescue_kernel(
    const float* __restrict__ embed, const float* __restrict__ prew,
    const float* __restrict__ preb, const float* __restrict__ CB,
    float* __restrict__ out_idx)
{
    const int row = blockIdx.x;
    if (g_gap[row] >= TAU) return;
    if (g_gap2[row] >= TAU2) return;

    __shared__ float erow[HH];
    __shared__ double zrow[DD];
    __shared__ double wsc[8];
    __shared__ int    widx[8];
    const int tid = threadIdx.x, wid = tid >> 5, lane = tid & 31;

    for (int i = tid; i < HH / 4; i += 256)
        ((float4*)erow)[i] = ((const float4*)(embed + (size_t)row * HH))[i];
    __syncthreads();

    {
        const float* w = prew + (size_t)tid * HH;
        double s = 0.0;
        for (int k = 0; k < HH; k++)
            s = fma((double)erow[k], (double)w[k], s);
        zrow[tid] = s + (double)preb[tid];
    }
    __syncthreads();

    double best = 1e300;
    int bidx = 0x7FFFFFFF;
    for (int c = wid; c < KK; c += 8) {
        const float* cp = CB + (size_t)c * DD;
        double dot = 0.0, cc = 0.0;
        for (int i = lane; i < DD; i += 32) {
            double cv = (double)cp[i];
            dot = fma(cv, zrow[i], dot);
            cc  = fma(cv, cv, cc);
        }
#pragma unroll
        for (int o = 16; o; o >>= 1) {
            dot += __shfl_xor_sync(0xFFFFFFFFu, dot, o);
            cc  += __shfl_xor_sync(0xFFFFFFFFu, cc, o);
        }
        double sc = cc - 2.0 * dot;
        if (sc < best || (sc == best && c < bidx)) { best = sc; bidx = c; }
    }
    if (lane == 0) { wsc[wid] = best; widx[wid] = bidx; }
    __syncthreads();
    if (tid == 0) {
        double b = wsc[0]; int bi = widx[0];
#pragma unroll
        for (int i = 1; i < 8; i++)
            if (wsc[i] < b || (wsc[i] == b && widx[i] < bi)) { b = wsc[i]; bi = widx[i]; }
        g_idx[row] = bi;
        out_idx[row] = (float)bi;
    }
}

// ------------------------------------------------------------------ small kernels
__global__ __launch_bounds__(256) void cnorm_kernel(const float* __restrict__ CB)
{
    int w = threadIdx.x >> 5;
    int lane = threadIdx.x & 31;
    int row = blockIdx.x * 8 + w;
    const float4* p = (const float4*)(CB + (size_t)row * DD);
    float s = 0.f;
#pragma unroll
    for (int i = 0; i < 2; i++) {
        float4 v = p[lane + i * 32];
        s += v.x * v.x + v.y * v.y + v.z * v.z + v.w * v.w;
    }
#pragma unroll
    for (int o = 16; o; o >>= 1) s += __shfl_xor_sync(0xFFFFFFFFu, s, o);
    if (!lane) g_cnorm[row] = s;
}

__global__ __launch_bounds__(256) void vq_partial(const float* __restrict__ CB)
{
    __shared__ float red[256];
    const int tid = threadIdx.x;
    const int bid = blockIdx.x;
    const int sub = tid >> 6;
    const int d4 = tid & 63;
    float acc = 0.f;
    for (int rr = 0; rr < 32; rr++) {
        int row = bid * 128 + rr * 4 + sub;
        int code = g_idx[row];
        float4 zv = *(const float4*)(g_z + (size_t)row * DD + d4 * 4);
        float4 cv = *(const float4*)(CB + (size_t)code * DD + d4 * 4);
        float dx = cv.x - zv.x, dy = cv.y - zv.y;
        float dz = cv.z - zv.z, dw = cv.w - zv.w;
        acc += dx * dx + dy * dy + dz * dz + dw * dw;
    }
    red[tid] = acc;
    __syncthreads();
    for (int s = 128; s; s >>= 1) {
        if (tid < s) red[tid] += red[tid + s];
        __syncthreads();
    }
    if (!tid) g_partial[bid] = red[0];
}

__global__ __launch_bounds__(1024) void finalize_kernel(const float* __restrict__ prior,
                                                        float* __restrict__ out)
{
    __shared__ float red[1024];
    const int tid = threadIdx.x;

    float m = -1e30f;
    for (int k = tid; k < KK; k += 1024) m = fmaxf(m, prior[k]);
    red[tid] = m;
    __syncthreads();
    for (int s = 512; s; s >>= 1) {
        if (tid < s) red[tid] = fmaxf(red[tid], red[tid + s]);
        __syncthreads();
    }
    float mx = red[0];
    __syncthreads();

    float se = 0.f;
    for (int k = tid; k < KK; k += 1024) se += expf(prior[k] - mx);
    red[tid] = se;
    __syncthreads();
    for (int s = 512; s; s >>= 1) {
        if (tid < s) red[tid] += red[tid + s];
        __syncthreads();
    }
    float logZ = mx + logf(red[0]);
    __syncthreads();

    float sp = 0.f;
    for (int n = tid; n < NN; n += 1024) sp += prior[g_idx[n]];
    red[tid] = sp;
    __syncthreads();
    for (int s = 512; s; s >>= 1) {
        if (tid < s) red[tid] += red[tid + s];
        __syncthreads();
    }
    float SP = red[0];
    __syncthreads();

    red[tid] = (tid < 256) ? g_partial[tid] : 0.f;
    __syncthreads();
    for (int s = 512; s; s >>= 1) {
        if (tid < s) red[tid] += red[tid + s];
        __syncthreads();
    }
    if (!tid) {
        float rate = ((float)NN * logZ - SP) * 1.4426950408889634f;
        float vq = 1.25f * red[0] / ((float)NN * (float)DD);
        out[(size_t)NN * HH + NN]     = rate;
        out[(size_t)NN * HH + NN + 1] = vq;
    }
}

// ------------------------------------------------------------------ launch
extern "C" void kernel_launch(void* const* d_in, const int* in_sizes, int n_in,
                              void* d_out, int out_size)
{
    const float* embed    = (const float*)d_in[0];
    const float* pre_w    = (const float*)d_in[1];
    const float* pre_b    = (const float*)d_in[2];
    const float* codebook = (const float*)d_in[3];
    const float* post_w   = (const float*)d_in[4];
    const float* post_b   = (const float*)d_in[5];
    const float* prior    = (const float*)d_in[6];
    float* out = (float*)d_out;

    cudaFuncSetAttribute(mm_kernel<0>, cudaFuncAttributeMaxDynamicSharedMemorySize, DSMEM);
    cudaFuncSetAttribute(mm_kernel<1>, cudaFuncAttributeMaxDynamicSharedMemorySize, DSMEM);
    cudaFuncSetAttribute(mm_kernel<2>, cudaFuncAttributeMaxDynamicSharedMemorySize, DSMEM);

    split_kernel<0><<<4096, 256>>>(embed,   (size_t)NN * HH / 8);
    split_kernel<1><<<512, 256>>>(pre_w,    (size_t)DD * HH / 8);
    split_kernel<2><<<512, 256>>>(codebook, (size_t)KK * DD / 8);
    split_kernel<3><<<512, 256>>>(post_w,   (size_t)HH * DD / 8);
    cnorm_kernel<<<KK / 8, 256>>>(codebook);

    // z = embed @ pre_w.T + pre_b (2-pass)
    mm_kernel<0><<<dim3(NN / 128, 2), 512, DSMEM>>>(pre_b, nullptr);
    split_kernel<4><<<1024, 256>>>(nullptr, (size_t)NN * DD / 8);

    // fused distance GEMM + argmin (2-pass) + gap
    mm_kernel<1><<<dim3(NN / 128, 1), 512, DSMEM>>>(nullptr, out + (size_t)NN * HH);

    // tiered rescue: fp32 exact-from-g_z, then fp64 exact-from-embed
    rescue32_kernel<<<NN, 256>>>(codebook, out + (size_t)NN * HH);
    rescue_kernel<<<NN, 256>>>(embed, pre_w, pre_b, codebook, out + (size_t)NN * HH);

    // embed_hat = codebook[idx] @ post_w.T + post_b (2-pass)
    mm_kernel<2><<<dim3(NN / 128, 16), 512, DSMEM>>>(post_b, out);

    vq_partial<<<256, 256>>>(codebook);
    finalize_kernel<<<1, 1024>>>(prior, out);
}

// round 17
// speedup vs baseline: 2.1672x; 2.1672x over previous
#include <cuda_runtime.h>
#include <cuda_fp16.h>
#include <cstdint>

#define NN 32768
#define HH 2048
#define DD 256
#define KK 4096
#define TAU 0.06f
#define TAU2 5e-4f

typedef unsigned long long u64;

// ------------------------------------------------------------------ scratch
__device__ float g_z[(size_t)NN * DD];
__device__ int   g_idx[NN];
__device__ float g_gap[NN];
__device__ float g_gap2[NN];
__device__ float g_cnorm[KK];
__device__ float g_partial[256];

__device__ __align__(16) __half g_embS[2][(size_t)NN * HH];
__device__ __align__(16) __half g_zS[2][(size_t)NN * DD];
__device__ __align__(16) __half g_cbS[2][(size_t)KK * DD];
__device__ __align__(16) __half g_pwS[2][(size_t)DD * HH];
__device__ __align__(16) __half g_qwS[2][(size_t)HH * DD];

// ------------------------------------------------------------------ helpers
__device__ __forceinline__ void ldm_x4(uint32_t (&r)[4], uint32_t addr) {
    asm volatile("ldmatrix.sync.aligned.m8n8.x4.shared.b16 {%0,%1,%2,%3}, [%4];"
                 : "=r"(r[0]), "=r"(r[1]), "=r"(r[2]), "=r"(r[3]) : "r"(addr));
}

__device__ __forceinline__ void mma16816(float (&d)[4], const uint32_t (&a)[4],
                                         uint32_t b0, uint32_t b1) {
    asm volatile(
        "mma.sync.aligned.m16n8k16.row.col.f32.f16.f16.f32 "
        "{%0,%1,%2,%3}, {%4,%5,%6,%7}, {%8,%9}, {%0,%1,%2,%3};"
        : "+f"(d[0]), "+f"(d[1]), "+f"(d[2]), "+f"(d[3])
        : "r"(a[0]), "r"(a[1]), "r"(a[2]), "r"(a[3]), "r"(b0), "r"(b1));
}

__device__ __forceinline__ void cp16(uint32_t saddr, const void* g) {
    asm volatile("cp.async.cg.shared.global [%0], [%1], 16;" :: "r"(saddr), "l"(g));
}

__device__ __forceinline__ u64 pack_key(float sc, int col) {
    unsigned u = __float_as_uint(sc);
    u = (u & 0x80000000u) ? ~u : (u | 0x80000000u);
    return ((u64)u << 32) | (unsigned)col;
}

__device__ __forceinline__ float key_score(u64 k) {
    unsigned u = (unsigned)(k >> 32);
    u = (u & 0x80000000u) ? (u & 0x7FFFFFFFu) : ~u;
    return __uint_as_float(u);
}

__device__ __forceinline__ void upd2(u64& m1, u64& m2, u64 key) {
    if (key < m1) { m2 = m1; m1 = key; }
    else if (key < m2) m2 = key;
}

__device__ __forceinline__ void merge2(u64& a1, u64& a2, u64 b1, u64 b2) {
    u64 n1, n2;
    if (a1 <= b1) { n1 = a1; n2 = (a2 < b1 ? a2 : b1); }
    else          { n1 = b1; n2 = (b2 < a1 ? b2 : a1); }
    a1 = n1; a2 = n2;
}

// ------------------------------------------------------------------ split (fp32 -> 2 fp16 planes)
template <int W>
__global__ __launch_bounds__(256) void split_kernel(const float* __restrict__ src_in, size_t n8)
{
    __half *p0, *p1;
    const float* src = src_in;
    if (W == 0)      { p0 = g_embS[0]; p1 = g_embS[1]; }
    else if (W == 1) { p0 = g_pwS[0];  p1 = g_pwS[1]; }
    else if (W == 2) { p0 = g_cbS[0];  p1 = g_cbS[1]; }
    else if (W == 3) { p0 = g_qwS[0];  p1 = g_qwS[1]; }
    else             { p0 = g_zS[0];   p1 = g_zS[1]; src = g_z; }

    for (size_t i = blockIdx.x * (size_t)blockDim.x + threadIdx.x; i < n8;
         i += (size_t)gridDim.x * blockDim.x) {
        float4 a = ((const float4*)src)[2 * i];
        float4 b = ((const float4*)src)[2 * i + 1];
        float v[8] = {a.x, a.y, a.z, a.w, b.x, b.y, b.z, b.w};
        unsigned short s0[8], s1[8];
#pragma unroll
        for (int j = 0; j < 8; j++) {
            float x = v[j];
            __half h0 = __float2half_rn(x);
            float r = x - __half2float(h0);
            __half h1 = __float2half_rn(r);
            s0[j] = __half_as_ushort(h0);
            s1[j] = __half_as_ushort(h1);
        }
        uint4 u0, u1;
        u0.x = s0[0] | ((uint32_t)s0[1] << 16); u0.y = s0[2] | ((uint32_t)s0[3] << 16);
        u0.z = s0[4] | ((uint32_t)s0[5] << 16); u0.w = s0[6] | ((uint32_t)s0[7] << 16);
        u1.x = s1[0] | ((uint32_t)s1[1] << 16); u1.y = s1[2] | ((uint32_t)s1[3] << 16);
        u1.z = s1[4] | ((uint32_t)s1[5] << 16); u1.w = s1[6] | ((uint32_t)s1[7] << 16);
        ((uint4*)p0)[i] = u0;
        ((uint4*)p1)[i] = u1;
    }
}

// ------------------------------------------------------------------ mma GEMM, 512 threads (16 warps, 32x32 warp tiles)
// MODE 0: z = embed @ pre_w.T + pre_b   (K=2048, 3 passes)
// MODE 1: argmin_k ||c||^2 - 2 z.c      (K=256, 2 passes, 32 n-tiles) + gap
// MODE 2: out = cb[idx] @ post_w.T + b  (K=256, 2 passes)
#define PLANEB 16384
#define STAGEB (4 * PLANEB)   // 64 KB stage (4 plane slots; p3 unused outside MODE 0)
#define DSMEM  (2 * STAGEB)   // 128 KB

template <int MODE>
__global__ __launch_bounds__(512, 1) void mm_kernel(const float* __restrict__ bias,
                                                    float* __restrict__ Cout)
{
    constexpr int Kd  = (MODE == 0) ? HH : DD;
    constexpr int KCH = Kd / 64;
    constexpr int NT  = (MODE == 1) ? (KK / 128) : 1;
    constexpr int TOT = KCH * NT;
    constexpr int NB  = (MODE == 0) ? 2 : 1;
    constexpr int NPASS = (MODE == 0) ? 3 : 2;
    constexpr size_t SA = (MODE == 0) ? (size_t)NN * HH
                        : (MODE == 1) ? (size_t)NN * DD : (size_t)KK * DD;
    constexpr size_t SB = (MODE == 0) ? (size_t)DD * HH
                        : (MODE == 1) ? (size_t)KK * DD : (size_t)HH * DD;

    extern __shared__ __align__(1024) char dsm[];
    __shared__ int rmap[128];
    __shared__ u64 red1[128][4];
    __shared__ u64 red2[128][4];

    const int tid = threadIdx.x;
    const int wid = tid >> 5, lane = tid & 31;
    const int wm = wid >> 2, wn = wid & 3;        // 4x4 warp grid, 32x32 tiles
    const int m0 = blockIdx.x * 128;
    const int n0b = blockIdx.y * 128;

    const __half* Abase =
        (MODE == 0) ? g_embS[0] : (MODE == 1) ? g_zS[0] : g_cbS[0];
    const __half* Bbase =
        (MODE == 0) ? g_pwS[0] : (MODE == 1) ? g_cbS[0] : g_qwS[0];

    if (MODE == 2) {
        if (tid < 128) rmap[tid] = g_idx[m0 + tid];
        __syncthreads();
    }

    const uint32_t dsm_u = (uint32_t)__cvta_generic_to_shared(dsm);

    auto issue = [&](int s) {
        const int nt = s / KCH;
        const int k0 = (s % KCH) * 64;
        const int n0 = (MODE == 1) ? nt * 128 : n0b;
        const uint32_t st = dsm_u + (s & 1) * STAGEB;
#pragma unroll
        for (int i = 0; i < 8; i++) {
            int lin = tid + i * 512;          // 0..4095 = 4 planes x 128 rows x 8 ch
            int p = lin >> 10, rem = lin & 1023, row = rem >> 3, ch = rem & 7;
            if (MODE != 0 && p == 3) continue;
            const __half* g;
            if (p < 2) {
                int grow = (MODE == 2) ? rmap[row] : (m0 + row);
                g = Abase + (size_t)p * SA + (size_t)grow * Kd + k0 + ch * 8;
            } else {
                g = Bbase + (size_t)(p - 2) * SB + (size_t)(n0 + row) * Kd + k0 + ch * 8;
            }
            uint32_t sa = st + p * PLANEB + row * 128 + ((ch ^ (row & 7)) << 4);
            cp16(sa, g);
        }
        asm volatile("cp.async.commit_group;");
    };

    float acc[2][4][4];
#pragma unroll
    for (int mt = 0; mt < 2; mt++)
#pragma unroll
        for (int nf = 0; nf < 4; nf++)
#pragma unroll
            for (int q = 0; q < 4; q++) acc[mt][nf][q] = 0.f;

    u64 rm1[2][2], rm2[2][2];
    if (MODE == 1) {
#pragma unroll
        for (int mt = 0; mt < 2; mt++)
#pragma unroll
            for (int h = 0; h < 2; h++) { rm1[mt][h] = ~0ULL; rm2[mt][h] = ~0ULL; }
    }

    issue(0);
    issue(1);

    for (int s = 0; s < TOT; s++) {
        if (s == TOT - 1) asm volatile("cp.async.wait_group 0;");
        else              asm volatile("cp.async.wait_group 1;");
        __syncthreads();

        const uint32_t sbase = dsm_u + (s & 1) * STAGEB;
#pragma unroll
        for (int kk = 0; kk < 4; kk++) {
            uint32_t Af[2][2][4];
            uint32_t Bf[NB][2][4];
#pragma unroll
            for (int p = 0; p < 2; p++)
#pragma unroll
                for (int mt = 0; mt < 2; mt++) {
                    int row = wm * 32 + mt * 16 + (lane & 15);
                    int ch = kk * 2 + (lane >> 4);
                    ldm_x4(Af[p][mt],
                           sbase + p * PLANEB + row * 128 + ((ch ^ (row & 7)) << 4));
                }
#pragma unroll
            for (int p = 0; p < NB; p++)
#pragma unroll
                for (int n2 = 0; n2 < 2; n2++) {
                    int row = wn * 32 + n2 * 16 + (lane & 7) + ((lane >> 4) << 3);
                    int ch = kk * 2 + ((lane >> 3) & 1);
                    ldm_x4(Bf[p][n2],
                           sbase + (2 + p) * PLANEB + row * 128 + ((ch ^ (row & 7)) << 4));
                }
            // MODE 0: a0b0, a0b1, a1b0.  MODE 1/2: a0b0, a1b0.
            const int pa[3] = {0, (MODE == 0) ? 0 : 1, 1};
            const int pb[3] = {0, (MODE == 0) ? 1 : 0, 0};
#pragma unroll
            for (int pp = 0; pp < NPASS; pp++)
#pragma unroll
                for (int mt = 0; mt < 2; mt++)
#pragma unroll
                    for (int nf = 0; nf < 4; nf++)
                        mma16816(acc[mt][nf], Af[pa[pp]][mt],
                                 Bf[pb[pp]][nf >> 1][(nf & 1) * 2],
                                 Bf[pb[pp]][nf >> 1][(nf & 1) * 2 + 1]);
        }

        if (MODE == 1 && (s % KCH) == KCH - 1) {
            const int nt = s / KCH;
#pragma unroll
            for (int nf = 0; nf < 4; nf++) {
                int col = nt * 128 + wn * 32 + nf * 8 + (lane & 3) * 2;
                float cn0 = __ldg(&g_cnorm[col]);
                float cn1 = __ldg(&g_cnorm[col + 1]);
#pragma unroll
                for (int mt = 0; mt < 2; mt++) {
                    upd2(rm1[mt][0], rm2[mt][0], pack_key(cn0 - 2.f * acc[mt][nf][0], col));
                    upd2(rm1[mt][0], rm2[mt][0], pack_key(cn1 - 2.f * acc[mt][nf][1], col + 1));
                    upd2(rm1[mt][1], rm2[mt][1], pack_key(cn0 - 2.f * acc[mt][nf][2], col));
                    upd2(rm1[mt][1], rm2[mt][1], pack_key(cn1 - 2.f * acc[mt][nf][3], col + 1));
                    acc[mt][nf][0] = 0.f; acc[mt][nf][1] = 0.f;
                    acc[mt][nf][2] = 0.f; acc[mt][nf][3] = 0.f;
                }
            }
        }

        __syncthreads();
        if (s + 2 < TOT) issue(s + 2);
    }

    if (MODE == 1) {
        // each (row, wn) cell written by exactly one warp; merge across wn
#pragma unroll
        for (int mt = 0; mt < 2; mt++)
#pragma unroll
            for (int h = 0; h < 2; h++) {
                u64 a1 = rm1[mt][h], a2 = rm2[mt][h];
#pragma unroll
                for (int off = 1; off <= 2; off <<= 1) {
                    u64 b1 = __shfl_xor_sync(0xFFFFFFFFu, a1, off);
                    u64 b2 = __shfl_xor_sync(0xFFFFFFFFu, a2, off);
                    merge2(a1, a2, b1, b2);
                }
                if ((lane & 3) == 0) {
                    int r = wm * 32 + mt * 16 + h * 8 + (lane >> 2);
                    red1[r][wn] = a1;
                    red2[r][wn] = a2;
                }
            }
        __syncthreads();
        if (tid < 128) {
            u64 a1 = red1[tid][0], a2 = red2[tid][0];
#pragma unroll
            for (int j = 1; j < 4; j++) merge2(a1, a2, red1[tid][j], red2[tid][j]);
            int idx = (int)(a1 & 0xFFFFFFFFu);
            g_idx[m0 + tid] = idx;
            Cout[m0 + tid] = (float)idx;
            g_gap[m0 + tid] = key_score(a2) - key_score(a1);
        }
    } else {
        float* C = (MODE == 0) ? g_z : Cout;
        const int ldC = (MODE == 0) ? DD : HH;
#pragma unroll
        for (int mt = 0; mt < 2; mt++)
#pragma unroll
            for (int nf = 0; nf < 4; nf++) {
                int col = n0b + wn * 32 + nf * 8 + (lane & 3) * 2;
                int r0 = m0 + wm * 32 + mt * 16 + (lane >> 2);
                float b0v = __ldg(&bias[col]);
                float b1v = __ldg(&bias[col + 1]);
                float2 v0 = {acc[mt][nf][0] + b0v, acc[mt][nf][1] + b1v};
                float2 v1 = {acc[mt][nf][2] + b0v, acc[mt][nf][3] + b1v};
                *(float2*)&C[(size_t)r0 * ldC + col] = v0;
                *(float2*)&C[(size_t)(r0 + 8) * ldC + col] = v1;
            }
    }
}

// ------------------------------------------------------------------ tier-1 rescue: exact fp32 from g_z
__global__ __launch_bounds__(256) void rescue32_kernel(const float* __restrict__ CB,
                                                       float* __restrict__ out_idx)
{
    const int row = blockIdx.x;
    if (g_gap[row] >= TAU) return;

    __shared__ float zrow[DD];
    __shared__ u64 w1[8], w2[8];
    const int tid = threadIdx.x, wid = tid >> 5, lane = tid & 31;

    if (tid < DD / 4)
        ((float4*)zrow)[tid] = ((const float4*)(g_z + (size_t)row * DD))[tid];
    __syncthreads();

    u64 b1 = ~0ULL, b2 = ~0ULL;
    for (int c = wid; c < KK; c += 8) {
        const float4* cp = (const float4*)(CB + (size_t)c * DD);
        float s = 0.f;
#pragma unroll
        for (int i = 0; i < 2; i++) {
            float4 cv = cp[lane + 32 * i];
            float4 zv = ((const float4*)zrow)[lane + 32 * i];
            s += cv.x * zv.x + cv.y * zv.y + cv.z * zv.z + cv.w * zv.w;
        }
#pragma unroll
        for (int o = 16; o; o >>= 1) s += __shfl_xor_sync(0xFFFFFFFFu, s, o);
        upd2(b1, b2, pack_key(__ldg(&g_cnorm[c]) - 2.f * s, c));
    }
    if (lane == 0) { w1[wid] = b1; w2[wid] = b2; }
    __syncthreads();
    if (tid == 0) {
        u64 a1 = w1[0], a2 = w2[0];
#pragma unroll
        for (int i = 1; i < 8; i++) merge2(a1, a2, w1[i], w2[i]);
        int idx = (int)(a1 & 0xFFFFFFFFu);
        g_idx[row] = idx;
        out_idx[row] = (float)idx;
        g_gap2[row] = key_score(a2) - key_score(a1);
    }
}

// ------------------------------------------------------------------ tier-2 rescue: fp64 from embed (proven)
__global__ __launch_bounds__(256) void rescue_kernel(
    const float* __restrict__ embed, const float* __restrict__ prew,
    const float* __restrict__ preb, const float* __restrict__ CB,
    float* __restrict__ out_idx)
{
    const int row = blockIdx.x;
    if (g_gap[row] >= TAU) return;
    if (g_gap2[row] >= TAU2) return;

    __shared__ float erow[HH];
    __shared__ double zrow[DD];
    __shared__ double wsc[8];
    __shared__ int    widx[8];
    const int tid = threadIdx.x, wid = tid >> 5, lane = tid & 31;

    for (int i = tid; i < HH / 4; i += 256)
        ((float4*)erow)[i] = ((const float4*)(embed + (size_t)row * HH))[i];
    __syncthreads();

    {
        const float* w = prew + (size_t)tid * HH;
        double s = 0.0;
        for (int k = 0; k < HH; k++)
            s = fma((double)erow[k], (double)w[k], s);
        zrow[tid] = s + (double)preb[tid];
    }
    __syncthreads();

    double best = 1e300;
    int bidx = 0x7FFFFFFF;
    for (int c = wid; c < KK; c += 8) {
        const float* cp = CB + (size_t)c * DD;
        double dot = 0.0, cc = 0.0;
        for (int i = lane; i < DD; i += 32) {
            double cv = (double)cp[i];
            dot = fma(cv, zrow[i], dot);
            cc  = fma(cv, cv, cc);
        }
#pragma unroll
        for (int o = 16; o; o >>= 1) {
            dot += __shfl_xor_sync(0xFFFFFFFFu, dot, o);
            cc  += __shfl_xor_sync(0xFFFFFFFFu, cc, o);
        }
        double sc = cc - 2.0 * dot;
        if (sc < best || (sc == best && c < bidx)) { best = sc; bidx = c; }
    }
    if (lane == 0) { wsc[wid] = best; widx[wid] = bidx; }
    __syncthreads();
    if (tid == 0) {
        double b = wsc[0]; int bi = widx[0];
#pragma unroll
        for (int i = 1; i < 8; i++)
            if (wsc[i] < b || (wsc[i] == b && widx[i] < bi)) { b = wsc[i]; bi = widx[i]; }
        g_idx[row] = bi;
        out_idx[row] = (float)bi;
    }
}

// ------------------------------------------------------------------ small kernels
__global__ __launch_bounds__(256) void cnorm_kernel(const float* __restrict__ CB)
{
    int w = threadIdx.x >> 5;
    int lane = threadIdx.x & 31;
    int row = blockIdx.x * 8 + w;
    const float4* p = (const float4*)(CB + (size_t)row * DD);
    float s = 0.f;
#pragma unroll
    for (int i = 0; i < 2; i++) {
        float4 v = p[lane + i * 32];
        s += v.x * v.x + v.y * v.y + v.z * v.z + v.w * v.w;
    }
#pragma unroll
    for (int o = 16; o; o >>= 1) s += __shfl_xor_sync(0xFFFFFFFFu, s, o);
    if (!lane) g_cnorm[row] = s;
}

__global__ __launch_bounds__(256) void vq_partial(const float* __restrict__ CB)
{
    __shared__ float red[256];
    const int tid = threadIdx.x;
    const int bid = blockIdx.x;
    const int sub = tid >> 6;
    const int d4 = tid & 63;
    float acc = 0.f;
    for (int rr = 0; rr < 32; rr++) {
        int row = bid * 128 + rr * 4 + sub;
        int code = g_idx[row];
        float4 zv = *(const float4*)(g_z + (size_t)row * DD + d4 * 4);
        float4 cv = *(const float4*)(CB + (size_t)code * DD + d4 * 4);
        float dx = cv.x - zv.x, dy = cv.y - zv.y;
        float dz = cv.z - zv.z, dw = cv.w - zv.w;
        acc += dx * dx + dy * dy + dz * dz + dw * dw;
    }
    red[tid] = acc;
    __syncthreads();
    for (int s = 128; s; s >>= 1) {
        if (tid < s) red[tid] += red[tid + s];
        __syncthreads();
    }
    if (!tid) g_partial[bid] = red[0];
}

__global__ __launch_bounds__(1024) void finalize_kernel(const float* __restrict__ prior,
                                                        float* __restrict__ out)
{
    __shared__ float red[1024];
    const int tid = threadIdx.x;

    float m = -1e30f;
    for (int k = tid; k < KK; k += 1024) m = fmaxf(m, prior[k]);
    red[tid] = m;
    __syncthreads();
    for (int s = 512; s; s >>= 1) {
        if (tid < s) red[tid] = fmaxf(red[tid], red[tid + s]);
        __syncthreads();
    }
    float mx = red[0];
    __syncthreads();

    float se = 0.f;
    for (int k = tid; k < KK; k += 1024) se += expf(prior[k] - mx);
    red[tid] = se;
    __syncthreads();
    for (int s = 512; s; s >>= 1) {
        if (tid < s) red[tid] += red[tid + s];
        __syncthreads();
    }
    float logZ = mx + logf(red[0]);
    __syncthreads();

    float sp = 0.f;
    for (int n = tid; n < NN; n += 1024) sp += prior[g_idx[n]];
    red[tid] = sp;
    __syncthreads();
    for (int s = 512; s; s >>= 1) {
        if (tid < s) red[tid] += red[tid + s];
        __syncthreads();
    }
    float SP = red[0];
    __syncthreads();

    red[tid] = (tid < 256) ? g_partial[tid] : 0.f;
    __syncthreads();
    for (int s = 512; s; s >>= 1) {
        if (tid < s) red[tid] += red[tid + s];
        __syncthreads();
    }
    if (!tid) {
        float rate = ((float)NN * logZ - SP) * 1.4426950408889634f;
        float vq = 1.25f * red[0] / ((float)NN * (float)DD);
        out[(size_t)NN * HH + NN]     = rate;
        out[(size_t)NN * HH + NN + 1] = vq;
    }
}

// ------------------------------------------------------------------ launch
extern "C" void kernel_launch(void* const* d_in, const int* in_sizes, int n_in,
                              void* d_out, int out_size)
{
    const float* embed    = (const float*)d_in[0];
    const float* pre_w    = (const float*)d_in[1];
    const float* pre_b    = (const float*)d_in[2];
    const float* codebook = (const float*)d_in[3];
    const float* post_w   = (const float*)d_in[4];
    const float* post_b   = (const float*)d_in[5];
    const float* prior    = (const float*)d_in[6];
    float* out = (float*)d_out;

    cudaFuncSetAttribute(mm_kernel<0>, cudaFuncAttributeMaxDynamicSharedMemorySize, DSMEM);
    cudaFuncSetAttribute(mm_kernel<1>, cudaFuncAttributeMaxDynamicSharedMemorySize, DSMEM);
    cudaFuncSetAttribute(mm_kernel<2>, cudaFuncAttributeMaxDynamicSharedMemorySize, DSMEM);

    split_kernel<0><<<4096, 256>>>(embed,   (size_t)NN * HH / 8);
    split_kernel<1><<<512, 256>>>(pre_w,    (size_t)DD * HH / 8);
    split_kernel<2><<<512, 256>>>(codebook, (size_t)KK * DD / 8);
    split_kernel<3><<<512, 256>>>(post_w,   (size_t)HH * DD / 8);
    cnorm_kernel<<<KK / 8, 256>>>(codebook);

    // z = embed @ pre_w.T + pre_b (3-pass)
    mm_kernel<0><<<dim3(NN / 128, 2), 512, DSMEM>>>(pre_b, nullptr);
    split_kernel<4><<<1024, 256>>>(nullptr, (size_t)NN * DD / 8);

    // fused distance GEMM + argmin (2-pass) + gap
    mm_kernel<1><<<dim3(NN / 128, 1), 512, DSMEM>>>(nullptr, out + (size_t)NN * HH);

    // tiered rescue: fp32 exact-from-g_z, then fp64 exact-from-embed
    rescue32_kernel<<<NN, 256>>>(codebook, out + (size_t)NN * HH);
    rescue_kernel<<<NN, 256>>>(embed, pre_w, pre_b, codebook, out + (size_t)NN * HH);

    // embed_hat = codebook[idx] @ post_w.T + post_b (2-pass)
    mm_kernel<2><<<dim3(NN / 128, 16), 512, DSMEM>>>(post_b, out);

    vq_partial<<<256, 256>>>(codebook);
    finalize_kernel<<<1, 1024>>>(prior, out);
}